// round 1
// baseline (speedup 1.0000x reference)
#include <cuda_runtime.h>

#define BB 2
#define L1C 4096
#define L2C 6144
#define DM 256
#define NH 8
#define DH 32
#define QSCALE 0.1767766952966369f  /* 1/sqrt(32) */

// Scratch for projected Q/K/V (allocation-free rule: __device__ globals)
__device__ float g_Q[BB * L1C * DM];   // 8 MB
__device__ float g_K[BB * L2C * DM];   // 12 MB
__device__ float g_V[BB * L2C * DM];   // 12 MB

// ---------------------------------------------------------------------------
// Projection GEMM: out[m, n] = sum_k in[m, k] * W[n, k]   (torch Linear x@W^T)
// BM=64, BN=64, BK=32, 256 threads (16x16), 4x4 micro-tile.
// which: 0 -> g_Q, 1 -> g_K, 2 -> g_V
// ---------------------------------------------------------------------------
__global__ __launch_bounds__(256) void proj_kernel(
    const float* __restrict__ in, const float* __restrict__ W, int which)
{
    __shared__ float As[32][68];  // [k][m], pitch 68 keeps float4 rows 16B-aligned
    __shared__ float Bs[32][68];  // [k][n]

    float* __restrict__ out = (which == 0) ? g_Q : (which == 1) ? g_K : g_V;

    const int tid = threadIdx.x;
    const int ty = tid >> 4;      // 0..15 -> rows 4*ty..4*ty+3
    const int tx = tid & 15;      // 0..15 -> cols 4*tx..4*tx+3
    const int m0 = blockIdx.x * 64;
    const int n0 = blockIdx.y * 64;

    float acc[4][4] = {};

    for (int k0 = 0; k0 < DM; k0 += 32) {
#pragma unroll
        for (int i = 0; i < 8; i++) {
            int e = tid + i * 256;
            int r = e >> 5;       // 0..63
            int c = e & 31;       // 0..31  (warp covers one 128B row: coalesced)
            As[c][r] = in[(size_t)(m0 + r) * DM + k0 + c];
            Bs[c][r] = W[(size_t)(n0 + r) * DM + k0 + c];
        }
        __syncthreads();

#pragma unroll
        for (int kk = 0; kk < 32; kk++) {
            float4 a4 = *(const float4*)&As[kk][4 * ty];
            float4 b4 = *(const float4*)&Bs[kk][4 * tx];
            float av[4] = {a4.x, a4.y, a4.z, a4.w};
            float bv[4] = {b4.x, b4.y, b4.z, b4.w};
#pragma unroll
            for (int i = 0; i < 4; i++)
#pragma unroll
                for (int j = 0; j < 4; j++)
                    acc[i][j] += av[i] * bv[j];
        }
        __syncthreads();
    }

#pragma unroll
    for (int i = 0; i < 4; i++)
#pragma unroll
        for (int j = 0; j < 4; j++)
            out[(size_t)(m0 + 4 * ty + i) * DM + n0 + 4 * tx + j] = acc[i][j];
}

// ---------------------------------------------------------------------------
// Flash attention, fp32.
// Grid: (L1/64, B*NH). Block: 256 threads = 16x16.
//   S phase : thread (ty,tx) owns S[4ty..4ty+3][4tx..4tx+3]  (64x64 tile)
//   PV phase: thread (ty,tx) owns O[4ty..4ty+3][2tx..2tx+1]  (64x32 tile)
// Same ty -> same Q rows in both phases, so m/l/alpha stay in registers.
// A Q-row's S entries live in one 16-thread half-warp -> __syncwarp suffices
// between the P store and the PV read.
// ---------------------------------------------------------------------------
__global__ __launch_bounds__(256) void attn_kernel(float* __restrict__ out)
{
    __shared__ float Qs[32][68];  // [k][qrow]
    __shared__ float Ks[32][68];  // [k][key]
    __shared__ float Vs[64][34];  // [key][d]
    __shared__ float Ps[64][68];  // [key][qrow]

    const int tid = threadIdx.x;
    const int ty = tid >> 4;
    const int tx = tid & 15;
    const int bh = blockIdx.y;        // 0..15
    const int b = bh >> 3;
    const int h = bh & 7;
    const int q0 = blockIdx.x * 64;

    const float* __restrict__ Qg = g_Q + (size_t)b * L1C * DM + h * DH;
    const float* __restrict__ Kg = g_K + (size_t)b * L2C * DM + h * DH;
    const float* __restrict__ Vg = g_V + (size_t)b * L2C * DM + h * DH;

    // Load Q tile once, scale folded in. (Visible after first tile sync.)
#pragma unroll
    for (int i = 0; i < 8; i++) {
        int e = tid + i * 256;
        int r = e >> 5, c = e & 31;
        Qs[c][r] = Qg[(size_t)(q0 + r) * DM + c] * QSCALE;
    }

    float o[4][2] = {};
    float m[4], l[4];
#pragma unroll
    for (int i = 0; i < 4; i++) { m[i] = -1e30f; l[i] = 0.0f; }

    for (int kt = 0; kt < L2C / 64; kt++) {
        // ---- load K/V tiles (64 keys x 32 dims), coalesced 128B per warp ----
#pragma unroll
        for (int i = 0; i < 8; i++) {
            int e = tid + i * 256;
            int r = e >> 5, c = e & 31;
            size_t gofs = (size_t)(kt * 64 + r) * DM + c;
            Ks[c][r] = Kg[gofs];
            Vs[r][c] = Vg[gofs];
        }
        __syncthreads();

        // ---- S = Q * K^T for this tile ----
        float s[4][4] = {};
#pragma unroll
        for (int kk = 0; kk < 32; kk++) {
            float4 q4 = *(const float4*)&Qs[kk][4 * ty];
            float4 k4 = *(const float4*)&Ks[kk][4 * tx];
            float qv[4] = {q4.x, q4.y, q4.z, q4.w};
            float kv[4] = {k4.x, k4.y, k4.z, k4.w};
#pragma unroll
            for (int i = 0; i < 4; i++)
#pragma unroll
                for (int j = 0; j < 4; j++)
                    s[i][j] += qv[i] * kv[j];
        }

        // ---- online softmax (row reductions across the 16 tx lanes) ----
#pragma unroll
        for (int i = 0; i < 4; i++) {
            float rmax = fmaxf(fmaxf(s[i][0], s[i][1]), fmaxf(s[i][2], s[i][3]));
#pragma unroll
            for (int d = 1; d < 16; d <<= 1)
                rmax = fmaxf(rmax, __shfl_xor_sync(0xffffffffu, rmax, d));

            float mnew  = fmaxf(m[i], rmax);
            float alpha = __expf(m[i] - mnew);

            float psum = 0.0f;
#pragma unroll
            for (int j = 0; j < 4; j++) {
                float p = __expf(s[i][j] - mnew);
                s[i][j] = p;
                psum += p;
            }
#pragma unroll
            for (int d = 1; d < 16; d <<= 1)
                psum += __shfl_xor_sync(0xffffffffu, psum, d);

            l[i] = l[i] * alpha + psum;
            m[i] = mnew;
            o[i][0] *= alpha;
            o[i][1] *= alpha;

#pragma unroll
            for (int j = 0; j < 4; j++)
                Ps[4 * tx + j][4 * ty + i] = s[i][j];
        }
        __syncwarp();  // P produced & consumed within the same half-warp rows

        // ---- O += P * V ----
#pragma unroll 8
        for (int k = 0; k < 64; k++) {
            float4 p4 = *(const float4*)&Ps[k][4 * ty];    // broadcast per half-warp
            float2 v2 = *(const float2*)&Vs[k][2 * tx];    // conflict-free, 128B
            float pv[4] = {p4.x, p4.y, p4.z, p4.w};
#pragma unroll
            for (int i = 0; i < 4; i++) {
                o[i][0] += pv[i] * v2.x;
                o[i][1] += pv[i] * v2.y;
            }
        }
        __syncthreads();  // protect Ks/Vs/Ps before next tile's loads
    }

    // ---- normalize and write O ----
    float* __restrict__ Og = out + (size_t)b * L1C * DM + h * DH;
#pragma unroll
    for (int i = 0; i < 4; i++) {
        float inv = 1.0f / l[i];
        size_t row = (size_t)(q0 + 4 * ty + i) * DM;
        Og[row + 2 * tx + 0] = o[i][0] * inv;
        Og[row + 2 * tx + 1] = o[i][1] * inv;
    }
}

// ---------------------------------------------------------------------------
// Launch. Inputs (metadata order): x, source, Wq, Wk, Wv. Output fp32 [2,4096,256].
// Graph-capturable: kernel launches only, no sync, no alloc.
// ---------------------------------------------------------------------------
extern "C" void kernel_launch(void* const* d_in, const int* in_sizes, int n_in,
                              void* d_out, int out_size)
{
    const float* x   = (const float*)d_in[0];
    const float* src = (const float*)d_in[1];
    const float* Wq  = (const float*)d_in[2];
    const float* Wk  = (const float*)d_in[3];
    const float* Wv  = (const float*)d_in[4];
    float* out = (float*)d_out;

    dim3 blk(256);
    // Q: M = 2*4096 = 8192 rows -> grid (128, 4)
    proj_kernel<<<dim3(8192 / 64, DM / 64), blk>>>(x,   Wq, 0);
    // K, V: M = 2*6144 = 12288 rows -> grid (192, 4)
    proj_kernel<<<dim3(12288 / 64, DM / 64), blk>>>(src, Wk, 1);
    proj_kernel<<<dim3(12288 / 64, DM / 64), blk>>>(src, Wv, 2);

    attn_kernel<<<dim3(L1C / 64, BB * NH), blk>>>(out);
}

// round 2
// speedup vs baseline: 1.0020x; 1.0020x over previous
#include <cuda_runtime.h>

#define BB 2
#define L1C 4096
#define L2C 6144
#define DM 256
#define NH 8
#define DH 32
#define QSCALE 0.1767766952966369f  /* 1/sqrt(32) */

// Scratch for projected Q/K/V (allocation-free rule: __device__ globals)
__device__ float g_Q[BB * L1C * DM];   // 8 MB
__device__ float g_K[BB * L2C * DM];   // 12 MB
__device__ float g_V[BB * L2C * DM];   // 12 MB

// ---------------------------------------------------------------------------
// Projection GEMM: out[m, n] = sum_k in[m, k] * W[n, k]   (torch Linear x@W^T)
// BM=64, BN=64, BK=32, 256 threads (16x16), 4x4 micro-tile.
// which: 0 -> g_Q, 1 -> g_K, 2 -> g_V
// ---------------------------------------------------------------------------
__global__ __launch_bounds__(256) void proj_kernel(
    const float* __restrict__ in, const float* __restrict__ W, int which)
{
    __shared__ float As[32][68];  // [k][m], pitch 68 keeps float4 rows 16B-aligned
    __shared__ float Bs[32][68];  // [k][n]

    float* __restrict__ out = (which == 0) ? g_Q : (which == 1) ? g_K : g_V;

    const int tid = threadIdx.x;
    const int ty = tid >> 4;      // 0..15 -> rows 4*ty..4*ty+3
    const int tx = tid & 15;      // 0..15 -> cols 4*tx..4*tx+3
    const int m0 = blockIdx.x * 64;
    const int n0 = blockIdx.y * 64;

    float acc[4][4] = {};

    for (int k0 = 0; k0 < DM; k0 += 32) {
#pragma unroll
        for (int i = 0; i < 8; i++) {
            int e = tid + i * 256;
            int r = e >> 5;       // 0..63
            int c = e & 31;       // 0..31  (warp covers one 128B row: coalesced)
            As[c][r] = in[(size_t)(m0 + r) * DM + k0 + c];
            Bs[c][r] = W[(size_t)(n0 + r) * DM + k0 + c];
        }
        __syncthreads();

#pragma unroll
        for (int kk = 0; kk < 32; kk++) {
            float4 a4 = *(const float4*)&As[kk][4 * ty];
            float4 b4 = *(const float4*)&Bs[kk][4 * tx];
            float av[4] = {a4.x, a4.y, a4.z, a4.w};
            float bv[4] = {b4.x, b4.y, b4.z, b4.w};
#pragma unroll
            for (int i = 0; i < 4; i++)
#pragma unroll
                for (int j = 0; j < 4; j++)
                    acc[i][j] += av[i] * bv[j];
        }
        __syncthreads();
    }

#pragma unroll
    for (int i = 0; i < 4; i++)
#pragma unroll
        for (int j = 0; j < 4; j++)
            out[(size_t)(m0 + 4 * ty + i) * DM + n0 + 4 * tx + j] = acc[i][j];
}

// ---------------------------------------------------------------------------
// Flash attention, fp32.
// Grid: (L1/64, B*NH). Block: 256 threads = 16x16.
//   S phase : thread (ty,tx) owns S[4ty..4ty+3][4tx..4tx+3]  (64x64 tile)
//   PV phase: thread (ty,tx) owns O[4ty..4ty+3][2tx..2tx+1]  (64x32 tile)
// Same ty -> same Q rows in both phases, so m/l/alpha stay in registers.
// A Q-row's S entries live in one 16-thread half-warp -> __syncwarp suffices
// between the P store and the PV read.
// ---------------------------------------------------------------------------
__global__ __launch_bounds__(256) void attn_kernel(float* __restrict__ out)
{
    __shared__ float Qs[32][68];  // [k][qrow]
    __shared__ float Ks[32][68];  // [k][key]
    __shared__ float Vs[64][34];  // [key][d]
    __shared__ float Ps[64][68];  // [key][qrow]

    const int tid = threadIdx.x;
    const int ty = tid >> 4;
    const int tx = tid & 15;
    const int bh = blockIdx.y;        // 0..15
    const int b = bh >> 3;
    const int h = bh & 7;
    const int q0 = blockIdx.x * 64;

    const float* __restrict__ Qg = g_Q + (size_t)b * L1C * DM + h * DH;
    const float* __restrict__ Kg = g_K + (size_t)b * L2C * DM + h * DH;
    const float* __restrict__ Vg = g_V + (size_t)b * L2C * DM + h * DH;

    // Load Q tile once, scale folded in. (Visible after first tile sync.)
#pragma unroll
    for (int i = 0; i < 8; i++) {
        int e = tid + i * 256;
        int r = e >> 5, c = e & 31;
        Qs[c][r] = Qg[(size_t)(q0 + r) * DM + c] * QSCALE;
    }

    float o[4][2] = {};
    float m[4], l[4];
#pragma unroll
    for (int i = 0; i < 4; i++) { m[i] = -1e30f; l[i] = 0.0f; }

    for (int kt = 0; kt < L2C / 64; kt++) {
        // ---- load K/V tiles (64 keys x 32 dims), coalesced 128B per warp ----
#pragma unroll
        for (int i = 0; i < 8; i++) {
            int e = tid + i * 256;
            int r = e >> 5, c = e & 31;
            size_t gofs = (size_t)(kt * 64 + r) * DM + c;
            Ks[c][r] = Kg[gofs];
            Vs[r][c] = Vg[gofs];
        }
        __syncthreads();

        // ---- S = Q * K^T for this tile ----
        float s[4][4] = {};
#pragma unroll
        for (int kk = 0; kk < 32; kk++) {
            float4 q4 = *(const float4*)&Qs[kk][4 * ty];
            float4 k4 = *(const float4*)&Ks[kk][4 * tx];
            float qv[4] = {q4.x, q4.y, q4.z, q4.w};
            float kv[4] = {k4.x, k4.y, k4.z, k4.w};
#pragma unroll
            for (int i = 0; i < 4; i++)
#pragma unroll
                for (int j = 0; j < 4; j++)
                    s[i][j] += qv[i] * kv[j];
        }

        // ---- online softmax (row reductions across the 16 tx lanes) ----
#pragma unroll
        for (int i = 0; i < 4; i++) {
            float rmax = fmaxf(fmaxf(s[i][0], s[i][1]), fmaxf(s[i][2], s[i][3]));
#pragma unroll
            for (int d = 1; d < 16; d <<= 1)
                rmax = fmaxf(rmax, __shfl_xor_sync(0xffffffffu, rmax, d));

            float mnew  = fmaxf(m[i], rmax);
            float alpha = __expf(m[i] - mnew);

            float psum = 0.0f;
#pragma unroll
            for (int j = 0; j < 4; j++) {
                float p = __expf(s[i][j] - mnew);
                s[i][j] = p;
                psum += p;
            }
#pragma unroll
            for (int d = 1; d < 16; d <<= 1)
                psum += __shfl_xor_sync(0xffffffffu, psum, d);

            l[i] = l[i] * alpha + psum;
            m[i] = mnew;
            o[i][0] *= alpha;
            o[i][1] *= alpha;

#pragma unroll
            for (int j = 0; j < 4; j++)
                Ps[4 * tx + j][4 * ty + i] = s[i][j];
        }
        __syncwarp();  // P produced & consumed within the same half-warp rows

        // ---- O += P * V ----
#pragma unroll 8
        for (int k = 0; k < 64; k++) {
            float4 p4 = *(const float4*)&Ps[k][4 * ty];    // broadcast per half-warp
            float2 v2 = *(const float2*)&Vs[k][2 * tx];    // conflict-free, 128B
            float pv[4] = {p4.x, p4.y, p4.z, p4.w};
#pragma unroll
            for (int i = 0; i < 4; i++) {
                o[i][0] += pv[i] * v2.x;
                o[i][1] += pv[i] * v2.y;
            }
        }
        __syncthreads();  // protect Ks/Vs/Ps before next tile's loads
    }

    // ---- normalize and write O ----
    float* __restrict__ Og = out + (size_t)b * L1C * DM + h * DH;
#pragma unroll
    for (int i = 0; i < 4; i++) {
        float inv = 1.0f / l[i];
        size_t row = (size_t)(q0 + 4 * ty + i) * DM;
        Og[row + 2 * tx + 0] = o[i][0] * inv;
        Og[row + 2 * tx + 1] = o[i][1] * inv;
    }
}

// ---------------------------------------------------------------------------
// Launch. Inputs (metadata order): x, source, Wq, Wk, Wv. Output fp32 [2,4096,256].
// Graph-capturable: kernel launches only, no sync, no alloc.
// ---------------------------------------------------------------------------
extern "C" void kernel_launch(void* const* d_in, const int* in_sizes, int n_in,
                              void* d_out, int out_size)
{
    const float* x   = (const float*)d_in[0];
    const float* src = (const float*)d_in[1];
    const float* Wq  = (const float*)d_in[2];
    const float* Wk  = (const float*)d_in[3];
    const float* Wv  = (const float*)d_in[4];
    float* out = (float*)d_out;

    dim3 blk(256);
    // Q: M = 2*4096 = 8192 rows -> grid (128, 4)
    proj_kernel<<<dim3(8192 / 64, DM / 64), blk>>>(x,   Wq, 0);
    // K, V: M = 2*6144 = 12288 rows -> grid (192, 4)
    proj_kernel<<<dim3(12288 / 64, DM / 64), blk>>>(src, Wk, 1);
    proj_kernel<<<dim3(12288 / 64, DM / 64), blk>>>(src, Wv, 2);

    attn_kernel<<<dim3(L1C / 64, BB * NH), blk>>>(out);
}

// round 7
// speedup vs baseline: 3.4940x; 3.4868x over previous
#include <cuda_runtime.h>
#include <cuda_fp16.h>
#include <cstdint>

#define BB 2
#define L1C 4096
#define L2C 6144
#define DM 256
#define NH 8
/* 1/sqrt(32) * log2(e): softmax computed base-2 (EX2 only, no FMUL) */
#define QSCALE 0.2550890380315843f

// ---- device scratch (allocation-free rule) ----
__device__ __half g_xh[(size_t)BB * L1C * DM], g_xl[(size_t)BB * L1C * DM];
__device__ __half g_sh[(size_t)BB * L2C * DM], g_sl[(size_t)BB * L2C * DM];
__device__ __half g_wh[3 * DM * DM], g_wl[3 * DM * DM];
__device__ __half g_Q[(size_t)BB * L1C * DM];
__device__ __half g_K[(size_t)BB * L2C * DM];
__device__ __half g_Vh[(size_t)BB * L2C * DM], g_Vl[(size_t)BB * L2C * DM];

// mma.sync m16n8k16 row.col f32.f16.f16.f32, accumulate in place
#define MMA(c, a0, a1, a2, a3, b0, b1)                                        \
    asm volatile(                                                             \
        "mma.sync.aligned.m16n8k16.row.col.f32.f16.f16.f32 "                  \
        "{%0,%1,%2,%3}, {%4,%5,%6,%7}, {%8,%9}, {%0,%1,%2,%3};"               \
        : "+f"((c)[0]), "+f"((c)[1]), "+f"((c)[2]), "+f"((c)[3])              \
        : "r"(a0), "r"(a1), "r"(a2), "r"(a3), "r"(b0), "r"(b1))

__device__ __forceinline__ uint32_t h2u(float a, float b) {
    __half2 t = __floats2half2_rn(a, b);
    return *(uint32_t*)&t;
}

// ---------------------------------------------------------------------------
// Split fp32 -> fp16 hi + fp16 lo (hi+lo ~ fp32-accurate)
// ---------------------------------------------------------------------------
__global__ void split_kernel(const float* __restrict__ in,
                             __half* __restrict__ hi, __half* __restrict__ lo,
                             int n) {
    for (int i = blockIdx.x * 256 + threadIdx.x; i < n; i += gridDim.x * 256) {
        float v = in[i];
        __half h = __float2half_rn(v);
        hi[i] = h;
        lo[i] = __float2half_rn(v - __half2float(h));
    }
}

// ---------------------------------------------------------------------------
// Projection GEMM via mma: C[m][n] = sum_k X[m][k] * W[n][k]
// 3-term split: Xh*Wh + Xh*Wl + Xl*Wh  (fp32-grade accuracy)
// CTA: 64x64 tile, 128 threads (4 warps, each 16 rows x 64 cols)
// which: 0 -> g_Q (scaled by QSCALE incl. log2e), 1 -> g_K, 2 -> g_Vh/g_Vl
// ---------------------------------------------------------------------------
__global__ __launch_bounds__(128) void proj_kernel(
    const __half* __restrict__ Xh, const __half* __restrict__ Xl,
    const __half* __restrict__ Wh, const __half* __restrict__ Wl, int which) {
    __shared__ __half Ah[64][40], Al[64][40], Bh[64][40], Bl[64][40];
    const int tid = threadIdx.x, lane = tid & 31, w = tid >> 5;
    const int g = lane >> 2, tig = lane & 3;
    const int m0 = blockIdx.x * 64, n0 = blockIdx.y * 64;

    float c[8][4] = {};

    for (int k0 = 0; k0 < DM; k0 += 32) {
        __syncthreads();
#pragma unroll
        for (int i = 0; i < 4; i++) {
            int e = i * 128 + tid, r = e >> 3, c8 = e & 7;
            size_t ga = (size_t)(m0 + r) * DM + k0 + 4 * c8;
            size_t gb = (size_t)(n0 + r) * DM + k0 + 4 * c8;
            *(uint2*)&Ah[r][4 * c8] = *(const uint2*)&Xh[ga];
            *(uint2*)&Al[r][4 * c8] = *(const uint2*)&Xl[ga];
            *(uint2*)&Bh[r][4 * c8] = *(const uint2*)&Wh[gb];
            *(uint2*)&Bl[r][4 * c8] = *(const uint2*)&Wl[gb];
        }
        __syncthreads();
        const int row = w * 16 + g;
#pragma unroll
        for (int j = 0; j < 2; j++) {
            const int kd = 16 * j + 2 * tig;
            uint32_t ah0 = *(uint32_t*)&Ah[row][kd];
            uint32_t ah1 = *(uint32_t*)&Ah[row + 8][kd];
            uint32_t ah2 = *(uint32_t*)&Ah[row][kd + 8];
            uint32_t ah3 = *(uint32_t*)&Ah[row + 8][kd + 8];
            uint32_t al0 = *(uint32_t*)&Al[row][kd];
            uint32_t al1 = *(uint32_t*)&Al[row + 8][kd];
            uint32_t al2 = *(uint32_t*)&Al[row][kd + 8];
            uint32_t al3 = *(uint32_t*)&Al[row + 8][kd + 8];
#pragma unroll
            for (int n = 0; n < 8; n++) {
                const int key = 8 * n + g;
                uint32_t bh0 = *(uint32_t*)&Bh[key][kd];
                uint32_t bh1 = *(uint32_t*)&Bh[key][kd + 8];
                uint32_t bl0 = *(uint32_t*)&Bl[key][kd];
                uint32_t bl1 = *(uint32_t*)&Bl[key][kd + 8];
                MMA(c[n], ah0, ah1, ah2, ah3, bh0, bh1);
                MMA(c[n], ah0, ah1, ah2, ah3, bl0, bl1);
                MMA(c[n], al0, al1, al2, al3, bh0, bh1);
            }
        }
    }

#pragma unroll
    for (int n = 0; n < 8; n++)
#pragma unroll
        for (int i = 0; i < 2; i++) {
            size_t o = (size_t)(m0 + w * 16 + g + 8 * i) * DM + n0 + 8 * n + 2 * tig;
            float v0 = c[n][2 * i], v1 = c[n][2 * i + 1];
            if (which == 0) {
                *(__half2*)&g_Q[o] = __floats2half2_rn(v0 * QSCALE, v1 * QSCALE);
            } else if (which == 1) {
                *(__half2*)&g_K[o] = __floats2half2_rn(v0, v1);
            } else {
                __half h0 = __float2half_rn(v0), h1 = __float2half_rn(v1);
                *(__half2*)&g_Vh[o] = __halves2half2(h0, h1);
                *(__half2*)&g_Vl[o] = __floats2half2_rn(v0 - __half2float(h0),
                                                        v1 - __half2float(h1));
            }
        }
}

// ---------------------------------------------------------------------------
// Flash attention with mma. CTA: 64 q-rows, one (b,h); 128 threads (4 warps,
// warp owns 16 q-rows). KV tiles of 64 keys, 96 tiles, reg-prefetched.
// S = Q*K^T via mma (scores already in base-2 units); softmax via exp2f only;
// P re-packed to A-frags (no smem round trip); O += P*Vh + P*Vl.
// ---------------------------------------------------------------------------
__global__ __launch_bounds__(128, 3) void attn_kernel(float* __restrict__ out) {
    __shared__ __half Qs[64][40], Ks[64][40];
    __shared__ __half Vhs[32][72], Vls[32][72];

    const int tid = threadIdx.x, lane = tid & 31, w = tid >> 5;
    const int g = lane >> 2, tig = lane & 3;
    const int bh = blockIdx.y, b = bh >> 3, h = bh & 7;
    const int q0 = blockIdx.x * 64;

    const __half* __restrict__ Qg = g_Q + (size_t)b * L1C * DM + h * 32;
    const __half* __restrict__ Kg = g_K + (size_t)b * L2C * DM + h * 32;
    const __half* __restrict__ Vhg = g_Vh + (size_t)b * L2C * DM + h * 32;
    const __half* __restrict__ Vlg = g_Vl + (size_t)b * L2C * DM + h * 32;

    // cooperative Q tile load (scale incl. log2e already folded in proj)
#pragma unroll
    for (int i = 0; i < 4; i++) {
        int e = i * 128 + tid, r = e >> 3, c8 = e & 7;
        *(uint2*)&Qs[r][4 * c8] = *(const uint2*)&Qg[(size_t)(q0 + r) * DM + 4 * c8];
    }

    uint2 kr[4], vhr[4], vlr[4];
#define LOAD_TILE(t)                                                          \
    do {                                                                      \
        _Pragma("unroll") for (int i = 0; i < 4; i++) {                       \
            int e = i * 128 + tid, r = e >> 3, c8 = e & 7;                    \
            size_t ga = (size_t)((t) * 64 + r) * DM + 4 * c8;                 \
            kr[i] = *(const uint2*)&Kg[ga];                                   \
            vhr[i] = *(const uint2*)&Vhg[ga];                                 \
            vlr[i] = *(const uint2*)&Vlg[ga];                                 \
        }                                                                     \
    } while (0)
#define STORE_TILE()                                                          \
    do {                                                                      \
        _Pragma("unroll") for (int i = 0; i < 4; i++) {                       \
            int e = i * 128 + tid, r = e >> 3, c8 = e & 7;                    \
            *(uint2*)&Ks[r][4 * c8] = kr[i];                                  \
            __half* vh = (__half*)&vhr[i];                                    \
            __half* vl = (__half*)&vlr[i];                                    \
            _Pragma("unroll") for (int jj = 0; jj < 4; jj++) {                \
                Vhs[4 * c8 + jj][r] = vh[jj];                                 \
                Vls[4 * c8 + jj][r] = vl[jj];                                 \
            }                                                                 \
        }                                                                     \
    } while (0)

    LOAD_TILE(0);
    STORE_TILE();
    __syncthreads();

    // Q fragments (resident in regs for whole kernel)
    uint32_t qa[2][4];
    const int row = w * 16 + g;
#pragma unroll
    for (int j = 0; j < 2; j++) {
        const int kd = 16 * j + 2 * tig;
        qa[j][0] = *(uint32_t*)&Qs[row][kd];
        qa[j][1] = *(uint32_t*)&Qs[row + 8][kd];
        qa[j][2] = *(uint32_t*)&Qs[row][kd + 8];
        qa[j][3] = *(uint32_t*)&Qs[row + 8][kd + 8];
    }

    float o[4][4] = {};
    float mx0 = -1e30f, mx1 = -1e30f, l0 = 0.f, l1 = 0.f;

    for (int t = 0; t < L2C / 64; t++) {
        if (t < L2C / 64 - 1) LOAD_TILE(t + 1);  // overlap LDG with compute

        // ---- S = Q K^T (16 x 64 per warp), base-2 units ----
        float s[8][4] = {};
#pragma unroll
        for (int j = 0; j < 2; j++) {
            const int kd = 16 * j + 2 * tig;
#pragma unroll
            for (int n = 0; n < 8; n++) {
                uint32_t b0 = *(uint32_t*)&Ks[8 * n + g][kd];
                uint32_t b1 = *(uint32_t*)&Ks[8 * n + g][kd + 8];
                MMA(s[n], qa[j][0], qa[j][1], qa[j][2], qa[j][3], b0, b1);
            }
        }

        // ---- online softmax, base-2 (rows g and g+8; 4-lane reduction) ----
        float rm0 = -1e30f, rm1 = -1e30f;
#pragma unroll
        for (int n = 0; n < 8; n++) {
            rm0 = fmaxf(rm0, fmaxf(s[n][0], s[n][1]));
            rm1 = fmaxf(rm1, fmaxf(s[n][2], s[n][3]));
        }
        rm0 = fmaxf(rm0, __shfl_xor_sync(0xffffffffu, rm0, 1));
        rm0 = fmaxf(rm0, __shfl_xor_sync(0xffffffffu, rm0, 2));
        rm1 = fmaxf(rm1, __shfl_xor_sync(0xffffffffu, rm1, 1));
        rm1 = fmaxf(rm1, __shfl_xor_sync(0xffffffffu, rm1, 2));

        float mn0 = fmaxf(mx0, rm0), mn1 = fmaxf(mx1, rm1);
        float a0 = exp2f(mx0 - mn0), a1 = exp2f(mx1 - mn1);
        float ps0 = 0.f, ps1 = 0.f;
#pragma unroll
        for (int n = 0; n < 8; n++) {
            s[n][0] = exp2f(s[n][0] - mn0);
            s[n][1] = exp2f(s[n][1] - mn0);
            s[n][2] = exp2f(s[n][2] - mn1);
            s[n][3] = exp2f(s[n][3] - mn1);
            ps0 += s[n][0] + s[n][1];
            ps1 += s[n][2] + s[n][3];
        }
        ps0 += __shfl_xor_sync(0xffffffffu, ps0, 1);
        ps0 += __shfl_xor_sync(0xffffffffu, ps0, 2);
        ps1 += __shfl_xor_sync(0xffffffffu, ps1, 1);
        ps1 += __shfl_xor_sync(0xffffffffu, ps1, 2);

        l0 = l0 * a0 + ps0;
        l1 = l1 * a1 + ps1;
        mx0 = mn0;
        mx1 = mn1;
#pragma unroll
        for (int n = 0; n < 4; n++) {
            o[n][0] *= a0;
            o[n][1] *= a0;
            o[n][2] *= a1;
            o[n][3] *= a1;
        }

        // ---- pack P (C-frag layout == A-frag layout for m16k16) ----
        uint32_t pa[4][4];
#pragma unroll
        for (int j = 0; j < 4; j++) {
            pa[j][0] = h2u(s[2 * j][0], s[2 * j][1]);
            pa[j][1] = h2u(s[2 * j][2], s[2 * j][3]);
            pa[j][2] = h2u(s[2 * j + 1][0], s[2 * j + 1][1]);
            pa[j][3] = h2u(s[2 * j + 1][2], s[2 * j + 1][3]);
        }

        // ---- O += P * (Vh + Vl) ----
#pragma unroll
        for (int n = 0; n < 4; n++) {
#pragma unroll
            for (int j = 0; j < 4; j++) {
                const int kk = 16 * j + 2 * tig;
                uint32_t bh0 = *(uint32_t*)&Vhs[8 * n + g][kk];
                uint32_t bh1 = *(uint32_t*)&Vhs[8 * n + g][kk + 8];
                MMA(o[n], pa[j][0], pa[j][1], pa[j][2], pa[j][3], bh0, bh1);
                uint32_t bl0 = *(uint32_t*)&Vls[8 * n + g][kk];
                uint32_t bl1 = *(uint32_t*)&Vls[8 * n + g][kk + 8];
                MMA(o[n], pa[j][0], pa[j][1], pa[j][2], pa[j][3], bl0, bl1);
            }
        }
        __syncthreads();
        if (t < L2C / 64 - 1) {
            STORE_TILE();
            __syncthreads();
        }
    }

    // ---- epilogue ----
    float inv0 = 1.0f / l0, inv1 = 1.0f / l1;
    float* __restrict__ Og = out + (size_t)b * L1C * DM;
#pragma unroll
    for (int n = 0; n < 4; n++)
#pragma unroll
        for (int i = 0; i < 2; i++) {
            size_t oofs = (size_t)(q0 + row + 8 * i) * DM + h * 32 + 8 * n + 2 * tig;
            float inv = i ? inv1 : inv0;
            *(float2*)&Og[oofs] =
                make_float2(o[n][2 * i] * inv, o[n][2 * i + 1] * inv);
        }
}

// ---------------------------------------------------------------------------
extern "C" void kernel_launch(void* const* d_in, const int* in_sizes, int n_in,
                              void* d_out, int out_size) {
    const float* x = (const float*)d_in[0];
    const float* src = (const float*)d_in[1];
    const float* Wq = (const float*)d_in[2];
    const float* Wk = (const float*)d_in[3];
    const float* Wv = (const float*)d_in[4];
    float* out = (float*)d_out;

    __half *xh, *xl, *sh, *sl, *wh, *wl;
    cudaGetSymbolAddress((void**)&xh, g_xh);
    cudaGetSymbolAddress((void**)&xl, g_xl);
    cudaGetSymbolAddress((void**)&sh, g_sh);
    cudaGetSymbolAddress((void**)&sl, g_sl);
    cudaGetSymbolAddress((void**)&wh, g_wh);
    cudaGetSymbolAddress((void**)&wl, g_wl);

    const int NX = BB * L1C * DM, NS = BB * L2C * DM, NW = DM * DM;
    split_kernel<<<1024, 256>>>(x, xh, xl, NX);
    split_kernel<<<1024, 256>>>(src, sh, sl, NS);
    split_kernel<<<128, 256>>>(Wq, wh, wl, NW);
    split_kernel<<<128, 256>>>(Wk, wh + NW, wl + NW, NW);
    split_kernel<<<128, 256>>>(Wv, wh + 2 * NW, wl + 2 * NW, NW);

    dim3 blk(128);
    proj_kernel<<<dim3(NX / DM / 64, DM / 64), blk>>>(xh, xl, wh, wl, 0);
    proj_kernel<<<dim3(NS / DM / 64, DM / 64), blk>>>(sh, sl, wh + NW, wl + NW, 1);
    proj_kernel<<<dim3(NS / DM / 64, DM / 64), blk>>>(sh, sl, wh + 2 * NW, wl + 2 * NW, 2);

    attn_kernel<<<dim3(L1C / 64, BB * NH), blk>>>(out);
}

// round 10
// speedup vs baseline: 5.6264x; 1.6103x over previous
#include <cuda_runtime.h>
#include <cuda_fp16.h>
#include <cstdint>

#define BB 2
#define L1C 4096
#define L2C 6144
#define DM 256
#define NH 8
/* 1/sqrt(32) * log2(e): softmax computed base-2 (EX2 only) */
#define QSCALE 0.2550890380315843f

// ---- device scratch (allocation-free rule) ----
__device__ __half g_Q[(size_t)BB * L1C * DM];
__device__ __half g_K[(size_t)BB * L2C * DM];
__device__ __half g_V[(size_t)BB * L2C * DM];

// mma.sync m16n8k16 row.col f32.f16.f16.f32, accumulate in place
#define MMA(c, a0, a1, a2, a3, b0, b1)                                        \
    asm volatile(                                                             \
        "mma.sync.aligned.m16n8k16.row.col.f32.f16.f16.f32 "                  \
        "{%0,%1,%2,%3}, {%4,%5,%6,%7}, {%8,%9}, {%0,%1,%2,%3};"               \
        : "+f"((c)[0]), "+f"((c)[1]), "+f"((c)[2]), "+f"((c)[3])              \
        : "r"(a0), "r"(a1), "r"(a2), "r"(a3), "r"(b0), "r"(b1))

// exp2 of two floats via fp16x2 MUFU; result is packed half2 (P fragment ready)
__device__ __forceinline__ uint32_t hexp2(float x0, float x1) {
    __half2 hx = __floats2half2_rn(x0, x1);
    uint32_t r;
    asm("ex2.approx.f16x2 %0, %1;" : "=r"(r) : "r"(*(uint32_t*)&hx));
    return r;
}

// ---------------------------------------------------------------------------
// Projection GEMM via mma, fp32 inputs converted to hi/lo fp16 in-kernel.
// C[m][n] = sum_k X[m][k] * W[n][k];  3-term split Xh*Wh + Xh*Wl + Xl*Wh.
// CTA: 64x64 tile, 128 threads (4 warps). which: 0->g_Q(scaled) 1->g_K 2->g_V
// ---------------------------------------------------------------------------
__global__ __launch_bounds__(128) void proj_kernel(
    const float* __restrict__ X, const float* __restrict__ W, int which) {
    __shared__ __half Ah[64][40], Al[64][40], Bh[64][40], Bl[64][40];
    const int tid = threadIdx.x, lane = tid & 31, w = tid >> 5;
    const int g = lane >> 2, tig = lane & 3;
    const int m0 = blockIdx.x * 64, n0 = blockIdx.y * 64;

    float c[8][4] = {};

    for (int k0 = 0; k0 < DM; k0 += 32) {
        __syncthreads();
#pragma unroll
        for (int i = 0; i < 4; i++) {
            int e = i * 128 + tid, r = e >> 3, c8 = e & 7;
            float4 xv = *(const float4*)&X[(size_t)(m0 + r) * DM + k0 + 4 * c8];
            float4 wv = *(const float4*)&W[(size_t)(n0 + r) * DM + k0 + 4 * c8];
            __half2 xh0 = __floats2half2_rn(xv.x, xv.y);
            __half2 xh1 = __floats2half2_rn(xv.z, xv.w);
            __half2 wh0 = __floats2half2_rn(wv.x, wv.y);
            __half2 wh1 = __floats2half2_rn(wv.z, wv.w);
            *(__half2*)&Ah[r][4 * c8] = xh0;
            *(__half2*)&Ah[r][4 * c8 + 2] = xh1;
            *(__half2*)&Bh[r][4 * c8] = wh0;
            *(__half2*)&Bh[r][4 * c8 + 2] = wh1;
            *(__half2*)&Al[r][4 * c8] = __floats2half2_rn(
                xv.x - __low2float(xh0), xv.y - __high2float(xh0));
            *(__half2*)&Al[r][4 * c8 + 2] = __floats2half2_rn(
                xv.z - __low2float(xh1), xv.w - __high2float(xh1));
            *(__half2*)&Bl[r][4 * c8] = __floats2half2_rn(
                wv.x - __low2float(wh0), wv.y - __high2float(wh0));
            *(__half2*)&Bl[r][4 * c8 + 2] = __floats2half2_rn(
                wv.z - __low2float(wh1), wv.w - __high2float(wh1));
        }
        __syncthreads();
        const int row = w * 16 + g;
#pragma unroll
        for (int j = 0; j < 2; j++) {
            const int kd = 16 * j + 2 * tig;
            uint32_t ah0 = *(uint32_t*)&Ah[row][kd];
            uint32_t ah1 = *(uint32_t*)&Ah[row + 8][kd];
            uint32_t ah2 = *(uint32_t*)&Ah[row][kd + 8];
            uint32_t ah3 = *(uint32_t*)&Ah[row + 8][kd + 8];
            uint32_t al0 = *(uint32_t*)&Al[row][kd];
            uint32_t al1 = *(uint32_t*)&Al[row + 8][kd];
            uint32_t al2 = *(uint32_t*)&Al[row][kd + 8];
            uint32_t al3 = *(uint32_t*)&Al[row + 8][kd + 8];
#pragma unroll
            for (int n = 0; n < 8; n++) {
                const int key = 8 * n + g;
                uint32_t bh0 = *(uint32_t*)&Bh[key][kd];
                uint32_t bh1 = *(uint32_t*)&Bh[key][kd + 8];
                uint32_t bl0 = *(uint32_t*)&Bl[key][kd];
                uint32_t bl1 = *(uint32_t*)&Bl[key][kd + 8];
                MMA(c[n], ah0, ah1, ah2, ah3, bh0, bh1);
                MMA(c[n], ah0, ah1, ah2, ah3, bl0, bl1);
                MMA(c[n], al0, al1, al2, al3, bh0, bh1);
            }
        }
    }

#pragma unroll
    for (int n = 0; n < 8; n++)
#pragma unroll
        for (int i = 0; i < 2; i++) {
            size_t o = (size_t)(m0 + w * 16 + g + 8 * i) * DM + n0 + 8 * n + 2 * tig;
            float v0 = c[n][2 * i], v1 = c[n][2 * i + 1];
            if (which == 0) {
                *(__half2*)&g_Q[o] = __floats2half2_rn(v0 * QSCALE, v1 * QSCALE);
            } else if (which == 1) {
                *(__half2*)&g_K[o] = __floats2half2_rn(v0, v1);
            } else {
                *(__half2*)&g_V[o] = __floats2half2_rn(v0, v1);
            }
        }
}

// ---------------------------------------------------------------------------
// Flash attention with mma. CTA: 64 q-rows, one (b,h); 128 threads (4 warps).
// KV tiles of 64 keys, 96 tiles, double-buffered smem (1 sync/tile),
// register prefetch of next tile. Softmax base-2 via ex2.approx.f16x2 —
// fp16 P is produced directly; l sums exactly the p used in P*V.
// ---------------------------------------------------------------------------
__global__ __launch_bounds__(128, 4) void attn_kernel(float* __restrict__ out) {
    __shared__ __half Qs[64][40];
    __shared__ __half Ks[2][64][40];
    __shared__ __half Vs[2][32][72];

    const int tid = threadIdx.x, lane = tid & 31, w = tid >> 5;
    const int g = lane >> 2, tig = lane & 3;
    const int bh = blockIdx.y, b = bh >> 3, h = bh & 7;
    const int q0 = blockIdx.x * 64;

    const __half* __restrict__ Qg = g_Q + (size_t)b * L1C * DM + h * 32;
    const __half* __restrict__ Kg = g_K + (size_t)b * L2C * DM + h * 32;
    const __half* __restrict__ Vg = g_V + (size_t)b * L2C * DM + h * 32;

    // cooperative Q tile load (scale incl. log2e folded in proj)
#pragma unroll
    for (int i = 0; i < 4; i++) {
        int e = i * 128 + tid, r = e >> 3, c8 = e & 7;
        *(uint2*)&Qs[r][4 * c8] = *(const uint2*)&Qg[(size_t)(q0 + r) * DM + 4 * c8];
    }

    uint2 kr[4], vr[4];
#define LOAD_TILE(t)                                                          \
    do {                                                                      \
        _Pragma("unroll") for (int i = 0; i < 4; i++) {                       \
            int e = i * 128 + tid, r = e >> 3, c8 = e & 7;                    \
            size_t ga = (size_t)((t) * 64 + r) * DM + 4 * c8;                 \
            kr[i] = *(const uint2*)&Kg[ga];                                   \
            vr[i] = *(const uint2*)&Vg[ga];                                   \
        }                                                                     \
    } while (0)
#define STORE_TILE(buf)                                                       \
    do {                                                                      \
        _Pragma("unroll") for (int i = 0; i < 4; i++) {                       \
            int e = i * 128 + tid, r = e >> 3, c8 = e & 7;                    \
            *(uint2*)&Ks[buf][r][4 * c8] = kr[i];                             \
            __half* vv = (__half*)&vr[i];                                     \
            _Pragma("unroll") for (int jj = 0; jj < 4; jj++)                  \
                Vs[buf][4 * c8 + jj][r] = vv[jj];                             \
        }                                                                     \
    } while (0)

    LOAD_TILE(0);
    STORE_TILE(0);
    __syncthreads();

    // Q fragments resident in regs
    uint32_t qa[2][4];
    const int row = w * 16 + g;
#pragma unroll
    for (int j = 0; j < 2; j++) {
        const int kd = 16 * j + 2 * tig;
        qa[j][0] = *(uint32_t*)&Qs[row][kd];
        qa[j][1] = *(uint32_t*)&Qs[row + 8][kd];
        qa[j][2] = *(uint32_t*)&Qs[row][kd + 8];
        qa[j][3] = *(uint32_t*)&Qs[row + 8][kd + 8];
    }

    float o[4][4] = {};
    float mx0 = -1e30f, mx1 = -1e30f, l0 = 0.f, l1 = 0.f;

    const int NT = L2C / 64;
    for (int t = 0; t < NT; t++) {
        const int cur = t & 1;
        if (t < NT - 1) LOAD_TILE(t + 1);  // LDG prefetch into regs

        // ---- S = Q K^T (16 x 64 per warp), base-2 units ----
        float s[8][4] = {};
#pragma unroll
        for (int j = 0; j < 2; j++) {
            const int kd = 16 * j + 2 * tig;
#pragma unroll
            for (int n = 0; n < 8; n++) {
                uint32_t b0 = *(uint32_t*)&Ks[cur][8 * n + g][kd];
                uint32_t b1 = *(uint32_t*)&Ks[cur][8 * n + g][kd + 8];
                MMA(s[n], qa[j][0], qa[j][1], qa[j][2], qa[j][3], b0, b1);
            }
        }

        // ---- online softmax, base-2 ----
        float rm0 = -1e30f, rm1 = -1e30f;
#pragma unroll
        for (int n = 0; n < 8; n++) {
            rm0 = fmaxf(rm0, fmaxf(s[n][0], s[n][1]));
            rm1 = fmaxf(rm1, fmaxf(s[n][2], s[n][3]));
        }
        rm0 = fmaxf(rm0, __shfl_xor_sync(0xffffffffu, rm0, 1));
        rm0 = fmaxf(rm0, __shfl_xor_sync(0xffffffffu, rm0, 2));
        rm1 = fmaxf(rm1, __shfl_xor_sync(0xffffffffu, rm1, 1));
        rm1 = fmaxf(rm1, __shfl_xor_sync(0xffffffffu, rm1, 2));

        float mn0 = fmaxf(mx0, rm0), mn1 = fmaxf(mx1, rm1);
        float a0 = exp2f(mx0 - mn0), a1 = exp2f(mx1 - mn1);

        // exp via fp16x2 MUFU; pa IS the P fragment; l sums the same p bits
        uint32_t pa[4][4];
        float ps0 = 0.f, ps1 = 0.f;
#pragma unroll
        for (int j = 0; j < 4; j++) {
            pa[j][0] = hexp2(s[2 * j][0] - mn0, s[2 * j][1] - mn0);
            pa[j][1] = hexp2(s[2 * j][2] - mn1, s[2 * j][3] - mn1);
            pa[j][2] = hexp2(s[2 * j + 1][0] - mn0, s[2 * j + 1][1] - mn0);
            pa[j][3] = hexp2(s[2 * j + 1][2] - mn1, s[2 * j + 1][3] - mn1);
            float2 f0 = __half22float2(*(__half2*)&pa[j][0]);
            float2 f2 = __half22float2(*(__half2*)&pa[j][2]);
            ps0 += f0.x + f0.y + f2.x + f2.y;
            float2 f1 = __half22float2(*(__half2*)&pa[j][1]);
            float2 f3 = __half22float2(*(__half2*)&pa[j][3]);
            ps1 += f1.x + f1.y + f3.x + f3.y;
        }
        ps0 += __shfl_xor_sync(0xffffffffu, ps0, 1);
        ps0 += __shfl_xor_sync(0xffffffffu, ps0, 2);
        ps1 += __shfl_xor_sync(0xffffffffu, ps1, 1);
        ps1 += __shfl_xor_sync(0xffffffffu, ps1, 2);

        l0 = l0 * a0 + ps0;
        l1 = l1 * a1 + ps1;
        mx0 = mn0;
        mx1 = mn1;
#pragma unroll
        for (int n = 0; n < 4; n++) {
            o[n][0] *= a0;
            o[n][1] *= a0;
            o[n][2] *= a1;
            o[n][3] *= a1;
        }

        // ---- O += P * V ----
#pragma unroll
        for (int n = 0; n < 4; n++) {
#pragma unroll
            for (int j = 0; j < 4; j++) {
                const int kk = 16 * j + 2 * tig;
                uint32_t b0 = *(uint32_t*)&Vs[cur][8 * n + g][kk];
                uint32_t b1 = *(uint32_t*)&Vs[cur][8 * n + g][kk + 8];
                MMA(o[n], pa[j][0], pa[j][1], pa[j][2], pa[j][3], b0, b1);
            }
        }

        if (t < NT - 1) STORE_TILE((t + 1) & 1);  // fill other buffer
        __syncthreads();
    }

    // ---- epilogue ----
    float inv0 = 1.0f / l0, inv1 = 1.0f / l1;
    float* __restrict__ Og = out + (size_t)b * L1C * DM;
#pragma unroll
    for (int n = 0; n < 4; n++)
#pragma unroll
        for (int i = 0; i < 2; i++) {
            size_t oofs = (size_t)(q0 + row + 8 * i) * DM + h * 32 + 8 * n + 2 * tig;
            float inv = i ? inv1 : inv0;
            *(float2*)&Og[oofs] =
                make_float2(o[n][2 * i] * inv, o[n][2 * i + 1] * inv);
        }
}

// ---------------------------------------------------------------------------
extern "C" void kernel_launch(void* const* d_in, const int* in_sizes, int n_in,
                              void* d_out, int out_size) {
    const float* x = (const float*)d_in[0];
    const float* src = (const float*)d_in[1];
    const float* Wq = (const float*)d_in[2];
    const float* Wk = (const float*)d_in[3];
    const float* Wv = (const float*)d_in[4];
    float* out = (float*)d_out;

    dim3 blk(128);
    proj_kernel<<<dim3(BB * L1C / 64, DM / 64), blk>>>(x, Wq, 0);
    proj_kernel<<<dim3(BB * L2C / 64, DM / 64), blk>>>(src, Wk, 1);
    proj_kernel<<<dim3(BB * L2C / 64, DM / 64), blk>>>(src, Wv, 2);

    attn_kernel<<<dim3(L1C / 64, BB * NH), blk>>>(out);
}